// round 8
// baseline (speedup 1.0000x reference)
#include <cuda_runtime.h>

#define NN 20000
#define NE 320000
#define NG 256
#define NA 23
#define NB 7
#define M0 64
#define M1 24
#define M2 16
#define MDIM 64

__device__ __align__(16) float g_wv[3381];                 // WV[(jv*7+v)*23 + u]
__device__ __align__(16) float g_yv[(size_t)NN * 168];     // yv[n][jv(21)*8 + v(7)]
__device__ __align__(16) float g_ead[(size_t)NE * 8];      // dst-sorted ea, padded
__device__ __align__(16) float g_shd[(size_t)NE * 8];      // dst-sorted sh1(3),sh2(5)
__device__ __align__(16) float g_z[(size_t)NE * 24];       // z[e,jv] dst-sorted, padded
__device__ __align__(16) float g_m[(size_t)NN * MDIM];
__device__ int g_cnt_d[NN], g_cur_d[NN], g_start_d[NN];
__device__ int g_cnt_s[NN], g_cur_s[NN], g_start_s[NN];
__device__ int g_desrc[NE];
__device__ int g_seid[NE], g_spos[NE];

#define A1  0.078811041f
#define C0  0.047245559f
#define C1  0.044543540f
#define C2  0.042257713f
#define S3  1.7320508075688772f
#define S5  2.23606797749979f
#define S15 3.872983346207417f

__global__ void k_zero(float* __restrict__ out) {
    int i = blockIdx.x * blockDim.x + threadIdx.x;
    int stride = gridDim.x * blockDim.x;
    for (int j = i; j < NN; j += stride) { g_cnt_d[j] = 0; g_cnt_s[j] = 0; }
    for (int j = i; j < NG; j += stride) out[j] = 0.f;
}

__global__ void k_count(const int* __restrict__ ei) {
    int e = blockIdx.x * blockDim.x + threadIdx.x;
    if (e < NE) {
        atomicAdd(&g_cnt_s[ei[e]], 1);
        atomicAdd(&g_cnt_d[ei[NE + e]], 1);
    }
}

__global__ void __launch_bounds__(1024) k_scan() {
    __shared__ int sums[1024];
    int t = threadIdx.x;
    int base = t * 20;
    {
        int local[20]; int s = 0;
#pragma unroll
        for (int i = 0; i < 20; i++) {
            int idx = base + i;
            int c = (idx < NN) ? g_cnt_d[idx] : 0;
            local[i] = s; s += c;
        }
        sums[t] = s;
        __syncthreads();
        for (int d = 1; d < 1024; d <<= 1) {
            int v = (t >= d) ? sums[t - d] : 0;
            __syncthreads();
            if (t >= d) sums[t] += v;
            __syncthreads();
        }
        int excl = (t == 0) ? 0 : sums[t - 1];
#pragma unroll
        for (int i = 0; i < 20; i++) {
            int idx = base + i;
            if (idx < NN) { g_cur_d[idx] = excl + local[i]; g_start_d[idx] = excl + local[i]; }
        }
        __syncthreads();
    }
    {
        int local[20]; int s = 0;
#pragma unroll
        for (int i = 0; i < 20; i++) {
            int idx = base + i;
            int c = (idx < NN) ? g_cnt_s[idx] : 0;
            local[i] = s; s += c;
        }
        sums[t] = s;
        __syncthreads();
        for (int d = 1; d < 1024; d <<= 1) {
            int v = (t >= d) ? sums[t - d] : 0;
            __syncthreads();
            if (t >= d) sums[t] += v;
            __syncthreads();
        }
        int excl = (t == 0) ? 0 : sums[t - 1];
#pragma unroll
        for (int i = 0; i < 20; i++) {
            int idx = base + i;
            if (idx < NN) { g_cur_s[idx] = excl + local[i]; g_start_s[idx] = excl + local[i]; }
        }
    }
}

// fill: dst-sort staging (ea, sh, src); src-order: edge id + dst position
__global__ void k_fill(const int* __restrict__ ei, const float* __restrict__ ea,
                       const float* __restrict__ pos) {
    int e = blockIdx.x * blockDim.x + threadIdx.x;
    if (e >= NE) return;
    int src = ei[e];
    int dst = ei[NE + e];
    int pd = atomicAdd(&g_cur_d[dst], 1);
    g_desrc[pd] = src;

    float a0 = __ldg(ea + e*7 + 0), a1 = __ldg(ea + e*7 + 1);
    float a2 = __ldg(ea + e*7 + 2), a3 = __ldg(ea + e*7 + 3);
    float a4 = __ldg(ea + e*7 + 4), a5 = __ldg(ea + e*7 + 5);
    float a6 = __ldg(ea + e*7 + 6);
    float4* eap = (float4*)(g_ead + (size_t)pd * 8);
    eap[0] = make_float4(a0, a1, a2, a3);
    eap[1] = make_float4(a4, a5, a6, 0.f);

    float px = __ldg(pos + src*3+0) - __ldg(pos + dst*3+0);
    float py = __ldg(pos + src*3+1) - __ldg(pos + dst*3+1);
    float pz = __ldg(pos + src*3+2) - __ldg(pos + dst*3+2);
    float r2 = px*px + py*py + pz*pz;
    float4* shp = (float4*)(g_shd + (size_t)pd * 8);
    shp[0] = make_float4(S3*px, S3*py, S3*pz, S15*px*py);
    shp[1] = make_float4(S15*py*pz, 0.5f*S5*(3.f*pz*pz - r2),
                         S15*px*pz, 0.5f*S15*(px*px - py*py));

    int ps = atomicAdd(&g_cur_s[src], 1);
    g_seid[ps] = e;
    g_spos[ps] = pd;
}

// WV[(jv*7+v)*23+u] = scale_j * sum_w W_j[u,v,w] * V_j[w, v']
__global__ void k_wv(const float* __restrict__ W1, const float* __restrict__ W2,
                     const float* __restrict__ W3, const float* __restrict__ V1,
                     const float* __restrict__ V2, const float* __restrict__ V3) {
    int o = blockIdx.x * 512 + threadIdx.x;
    if (o >= 3381) return;
    int u = o % 23;
    int t = o / 23;
    int v = t % 7;
    int jv = t / 7;
    int j = jv / 7, vp = jv % 7;
    float r = 0.f;
    if (j == 0) {
        for (int w = 0; w < M0; w++) r = fmaf(W1[(u*7+v)*M0 + w], V1[w*7 + vp], r);
        r *= A1 * C0;
    } else if (j == 1) {
        for (int w = 0; w < M1; w++) r = fmaf(W2[(u*7+v)*M1 + w], V2[w*7 + vp], r);
        r *= A1 * C1;
    } else {
        for (int w = 0; w < M2; w++) r = fmaf(W3[(u*7+v)*M2 + w], V3[w*7 + vp], r);
        r *= A1 * C2;
    }
    g_wv[o] = r;
}

// yv[n, jv*8 + v] = sum_u x[n,u] * WV[(jv*7+v)*23 + u]
__global__ void __launch_bounds__(160) k_yv(const float* __restrict__ x) {
    __shared__ float xs[NA];
    int t = threadIdx.x;
    bool act = t < 147;
    float wreg[NA];
    if (act) {
#pragma unroll
        for (int u = 0; u < NA; u++) wreg[u] = g_wv[t * 23 + u];
    }
    int jv = t / 7, v = t % 7;
    int off = jv * 8 + v;
    for (int n = blockIdx.x; n < NN; n += gridDim.x) {
        __syncthreads();
        if (t < NA) xs[t] = x[n * NA + t];
        __syncthreads();
        if (!act) continue;
        float r = 0.f;
#pragma unroll
        for (int u = 0; u < NA; u++) r = fmaf(xs[u], wreg[u], r);
        g_yv[(size_t)n * 168 + off] = r;
    }
}

// zcomp: warp per SRC node; yv row resident in lane registers.
// z[e, jv] = sum_v ea[e,v] * yv[src, jv*8+v], stored at dst position.
__global__ void __launch_bounds__(256) k_zcomp(const float* __restrict__ ea) {
    int warp = (blockIdx.x * 256 + threadIdx.x) >> 5;
    int lane = threadIdx.x & 31;
    if (warp >= NN) return;
    int s = warp;
    bool act = lane < 21;

    float y0=0,y1=0,y2=0,y3=0,y4=0,y5=0,y6=0;
    if (act) {
        const float4* yp = (const float4*)(g_yv + (size_t)s * 168 + lane * 8);
        float4 p = __ldg(yp), q = __ldg(yp + 1);
        y0=p.x; y1=p.y; y2=p.z; y3=p.w; y4=q.x; y5=q.y; y6=q.z;
    }

    int start = g_start_s[s];
    int cnt = g_cnt_s[s];
    for (int i = 0; i < cnt; i++) {
        int e = g_seid[start + i];
        int pd = g_spos[start + i];
        const float* eap = ea + (size_t)e * 7;
        float a0 = __ldg(eap+0), a1 = __ldg(eap+1), a2 = __ldg(eap+2);
        float a3 = __ldg(eap+3), a4 = __ldg(eap+4), a5 = __ldg(eap+5);
        float a6 = __ldg(eap+6);
        float z = a0*y0;
        z = fmaf(a1, y1, z); z = fmaf(a2, y2, z); z = fmaf(a3, y3, z);
        z = fmaf(a4, y4, z); z = fmaf(a5, y5, z); z = fmaf(a6, y6, z);
        if (act) g_z[(size_t)pd * 24 + lane] = z;
    }
}

// maccum: warp per dst node; m[n,o] = sum_e sh(e,si(o)) * z(e,jv(o))
__global__ void __launch_bounds__(256) k_maccum() {
    int warp = (blockIdx.x * 256 + threadIdx.x) >> 5;
    int lane = threadIdx.x & 31;
    if (warp >= NN) return;
    int n = warp;
    int start = g_start_d[n];
    int cnt = g_cnt_d[n];

    int o0 = lane, o1 = lane + 32;
    int jv0, si0, jv1 = 0, si1 = 8;
    if (o0 < 7)       { jv0 = o0; si0 = 8; }
    else if (o0 < 28) { int q = o0 - 7;  jv0 = 7 + q / 3;  si0 = q % 3; }
    else              { int q = o0 - 28; jv0 = 14 + q / 5; si0 = 3 + q % 5; }
    bool v1ok = o1 < 63;
    if (v1ok) {
        if (o1 < 28) { int q = o1 - 7;  jv1 = 7 + q / 3;  si1 = q % 3; }
        else         { int q = o1 - 28; jv1 = 14 + q / 5; si1 = 3 + q % 5; }
    }

    float acc0 = 0.f, acc1 = 0.f;
    for (int i = 0; i < cnt; i++) {
        int base = start + i;
        const float* zp = g_z + (size_t)base * 24;
        const float* shp = g_shd + (size_t)base * 8;
        float z0 = __ldg(zp + jv0);
        float m0 = (si0 < 8) ? __ldg(shp + si0) : 1.f;
        acc0 = fmaf(z0, m0, acc0);
        if (v1ok) {
            float z1 = __ldg(zp + jv1);
            float m1 = (si1 < 8) ? __ldg(shp + si1) : 1.f;
            acc1 = fmaf(z1, m1, acc1);
        }
    }
    g_m[(size_t)n * MDIM + o0] = acc0;
    if (v1ok) g_m[(size_t)n * MDIM + o1] = acc1;
    else if (lane == 31) g_m[(size_t)n * MDIM + 63] = 0.f;
}

// pass2: warp per dst node, lane-per-output, coalesced m row loads.
// g(n) = sum_o sum_e ea[e,v(o)]*sh(e,si(o))*m[src_e, o]
__global__ void __launch_bounds__(256) k_pass2(
    const int* __restrict__ batch, float* __restrict__ out)
{
    int warp = (blockIdx.x * 256 + threadIdx.x) >> 5;
    int lane = threadIdx.x & 31;
    if (warp >= NN) return;
    int n = warp;
    int start = g_start_d[n];
    int cnt = g_cnt_d[n];

    int o0 = lane, o1 = lane + 32;
    int v0, si0, v1 = 0, si1 = 8;
    if (o0 < 7)       { v0 = o0; si0 = 8; }
    else if (o0 < 28) { int q = o0 - 7;  v0 = q / 3; si0 = q % 3; }
    else              { int q = o0 - 28; v0 = q / 5; si0 = 3 + q % 5; }
    bool v1ok = o1 < 63;
    if (v1ok) {
        if (o1 < 28) { int q = o1 - 7;  v1 = q / 3; si1 = q % 3; }
        else         { int q = o1 - 28; v1 = q / 5; si1 = 3 + q % 5; }
    }

    float acc0 = 0.f, acc1 = 0.f;
    for (int i = 0; i < cnt; i++) {
        int base = start + i;
        int s = g_desrc[base];                              // warp-broadcast
        const float* mrow = g_m + (size_t)s * MDIM;
        const float* eap = g_ead + (size_t)base * 8;
        const float* shp = g_shd + (size_t)base * 8;
        {
            float m = __ldg(mrow + o0);                     // coalesced
            float a = __ldg(eap + v0);
            float h = (si0 < 8) ? __ldg(shp + si0) : 1.f;
            acc0 = fmaf(m, a * h, acc0);
        }
        if (v1ok) {
            float m = __ldg(mrow + o1);
            float a = __ldg(eap + v1);
            float h = (si1 < 8) ? __ldg(shp + si1) : 1.f;
            acc1 = fmaf(m, a * h, acc1);
        }
    }

    float gsum = acc0 + acc1;
#pragma unroll
    for (int off = 16; off > 0; off >>= 1)
        gsum += __shfl_xor_sync(0xFFFFFFFFu, gsum, off);

    if (lane == 0) atomicAdd(&out[batch[n]], gsum);
}

extern "C" void kernel_launch(void* const* d_in, const int* in_sizes, int n_in,
                              void* d_out, int out_size) {
    const float* pos   = (const float*)d_in[0];
    const float* x     = (const float*)d_in[1];
    const float* ea    = (const float*)d_in[2];
    const int*   ei    = (const int*)d_in[3];
    const int*   batch = (const int*)d_in[4];
    const float* W1    = (const float*)d_in[5];
    const float* W2    = (const float*)d_in[6];
    const float* W3    = (const float*)d_in[7];
    const float* V1    = (const float*)d_in[8];
    const float* V2    = (const float*)d_in[9];
    const float* V3    = (const float*)d_in[10];
    float* out = (float*)d_out;

    k_zero<<<80, 256>>>(out);
    k_count<<<(NE + 255) / 256, 256>>>(ei);
    k_scan<<<1, 1024>>>();
    k_fill<<<(NE + 255) / 256, 256>>>(ei, ea, pos);
    k_wv<<<7, 512>>>(W1, W2, W3, V1, V2, V3);
    k_yv<<<1480, 160>>>(x);
    k_zcomp<<<(NN * 32 + 255) / 256, 256>>>(ea);
    k_maccum<<<(NN * 32 + 255) / 256, 256>>>();
    k_pass2<<<(NN * 32 + 255) / 256, 256>>>(batch, out);
}